// round 3
// baseline (speedup 1.0000x reference)
#include <cuda_runtime.h>
#include <math.h>

#define NN 50000
#define EE 800000
#define NF0 128
#define NF1 64
#define NF2 40
#define NCH 49   /* ceil(NN/1024) */

// ---------------- scratch (__device__ globals; allocation-free) ----------------
__device__ __align__(256) float g_P0[NN * NF0];   // M ⊙ (x @ W0)
__device__ __align__(256) float g_S0[NN * NF0];   // spmm(adjZ, P0)
__device__ __align__(256) float g_P1[NN * NF1];   // M ⊙ (h0 @ W1)
__device__ __align__(256) float g_S1[NN * NF1];   // spmm(adjZ, P1)
__device__ __align__(256) float g_P2[NN * NF2];   // h1 @ W2
__device__ __align__(256) int   g_rp[NN + 1];
__device__ __align__(256) int   g_deg[NN];
__device__ __align__(256) int   g_cur[NN];
__device__ __align__(256) int   g_colP[EE];
__device__ __align__(256) float g_vZ[EE];
__device__ __align__(256) float g_vA[EE];
__device__ __align__(256) int   g_part[NCH];

// ---------------- CSR build ----------------
__global__ void k_zero() {
    int i = blockIdx.x * blockDim.x + threadIdx.x;
    int stride = gridDim.x * blockDim.x;
    for (int j = i; j < NN; j += stride) { g_deg[j] = 0; g_cur[j] = 0; }
}

__global__ void k_hist(const int* __restrict__ row) {
    int e = blockIdx.x * blockDim.x + threadIdx.x;
    if (e < EE) atomicAdd(&g_deg[row[e]], 1);
}

__global__ void k_scan1() {   // per-chunk sums (chunk = 1024)
    __shared__ int sred[8];
    int base = blockIdx.x * 1024;
    int local = 0;
    #pragma unroll
    for (int j = 0; j < 4; ++j) {
        int i = base + threadIdx.x + j * 256;
        if (i < NN) local += g_deg[i];
    }
    for (int off = 16; off; off >>= 1) local += __shfl_down_sync(0xffffffffu, local, off);
    if ((threadIdx.x & 31) == 0) sred[threadIdx.x >> 5] = local;
    __syncthreads();
    if (threadIdx.x == 0) {
        int s = 0;
        #pragma unroll
        for (int w = 0; w < 8; ++w) s += sred[w];
        g_part[blockIdx.x] = s;
    }
}

__global__ void k_scan2() {   // scan the 49 partials
    int run = 0;
    for (int b = 0; b < NCH; ++b) { int t = g_part[b]; g_part[b] = run; run += t; }
    g_rp[NN] = run;
}

__global__ void k_scan3() {   // per-chunk exclusive scan + offset
    __shared__ int s[1024];
    int i = blockIdx.x * 1024 + threadIdx.x;
    int v = (i < NN) ? g_deg[i] : 0;
    s[threadIdx.x] = v;
    __syncthreads();
    for (int off = 1; off < 1024; off <<= 1) {
        int t = (threadIdx.x >= (unsigned)off) ? s[threadIdx.x - off] : 0;
        __syncthreads();
        s[threadIdx.x] += t;
        __syncthreads();
    }
    if (i < NN) g_rp[i] = g_part[blockIdx.x] + s[threadIdx.x] - v;
}

__global__ void k_scatter(const int* __restrict__ row, const int* __restrict__ col,
                          const float* __restrict__ vZ, const float* __restrict__ vA) {
    int e = blockIdx.x * blockDim.x + threadIdx.x;
    if (e >= EE) return;
    int r = row[e];
    int pos = g_rp[r] + atomicAdd(&g_cur[r], 1);
    g_colP[pos] = col[e];
    g_vZ[pos]   = vZ[e];
    g_vA[pos]   = vA[e];
}

// ---------------- GEMM 0: P0 = M ⊙ (x @ W0), K=128, NO=128 ----------------
__global__ void __launch_bounds__(128) k_gemm0(const float* __restrict__ x,
                                               const float* __restrict__ W0,
                                               const float* __restrict__ M) {
    __shared__ float Xs[32][128];
    __shared__ float Ws[32][128];
    int r0 = blockIdx.x * 32;
    int tid = threadIdx.x;
    const float4* xv4 = (const float4*)x;
    for (int i = tid; i < 1024; i += 128) {
        int rr = i >> 5, c4 = i & 31;
        int gr = r0 + rr;
        float4 v = (gr < NN) ? xv4[gr * 32 + c4] : make_float4(0.f, 0.f, 0.f, 0.f);
        *(float4*)&Xs[rr][c4 * 4] = v;
    }
    int tx = tid & 31, ty = tid >> 5;        // warp == one ty -> Xs broadcast
    float acc[8][4];
    #pragma unroll
    for (int i = 0; i < 8; ++i)
        #pragma unroll
        for (int j = 0; j < 4; ++j) acc[i][j] = 0.f;
    const float4* w4 = (const float4*)W0;
    for (int kc = 0; kc < 128; kc += 32) {
        __syncthreads();
        for (int i = tid; i < 1024; i += 128) {
            int rr = i >> 5, c4 = i & 31;
            *(float4*)&Ws[rr][c4 * 4] = w4[(kc + rr) * 32 + c4];
        }
        __syncthreads();
        #pragma unroll 8
        for (int k = 0; k < 32; ++k) {
            float wv[4];
            #pragma unroll
            for (int j = 0; j < 4; ++j) wv[j] = Ws[k][tx + 32 * j];
            #pragma unroll
            for (int i = 0; i < 8; ++i) {
                float xvv = Xs[ty * 8 + i][kc + k];
                #pragma unroll
                for (int j = 0; j < 4; ++j) acc[i][j] += xvv * wv[j];
            }
        }
    }
    #pragma unroll
    for (int i = 0; i < 8; ++i) {
        int gr = r0 + ty * 8 + i;
        if (gr < NN) {
            float m = M[gr];
            #pragma unroll
            for (int j = 0; j < 4; ++j) g_P0[gr * 128 + tx + 32 * j] = m * acc[i][j];
        }
    }
}

// ---------------- spmm width 128: S0[r] = sum vZ * P0[col] ----------------
__global__ void __launch_bounds__(256) k_spmm128() {
    int w = (blockIdx.x * 256 + threadIdx.x) >> 5;
    int lane = threadIdx.x & 31;
    if (w >= NN) return;
    int s = g_rp[w], e = g_rp[w + 1];
    float4 acc = make_float4(0.f, 0.f, 0.f, 0.f);
    const float4* Xv = (const float4*)g_P0;
    int j = s;
    for (; j + 1 < e; j += 2) {
        int c0 = g_colP[j], c1 = g_colP[j + 1];
        float v0 = g_vZ[j], v1 = g_vZ[j + 1];
        float4 a = Xv[c0 * 32 + lane];
        float4 b = Xv[c1 * 32 + lane];
        acc.x += v0 * a.x + v1 * b.x;
        acc.y += v0 * a.y + v1 * b.y;
        acc.z += v0 * a.z + v1 * b.z;
        acc.w += v0 * a.w + v1 * b.w;
    }
    if (j < e) {
        int c = g_colP[j]; float v = g_vZ[j];
        float4 a = Xv[c * 32 + lane];
        acc.x += v * a.x; acc.y += v * a.y; acc.z += v * a.z; acc.w += v * a.w;
    }
    ((float4*)g_S0)[w * 32 + lane] = acc;
}

// ------- GEMM 1: P1 = M ⊙ (relu(AM⊙S0 + b0) @ W1), K=128, NO=64 -------
__global__ void __launch_bounds__(128) k_gemm1(const float* __restrict__ AM,
                                               const float* __restrict__ b0,
                                               const float* __restrict__ W1,
                                               const float* __restrict__ M) {
    __shared__ float Xs[64][129];   // pad 129: 2 tys per warp -> distinct banks
    __shared__ float Ws[32][64];
    int r0 = blockIdx.x * 64;
    int tid = threadIdx.x;
    const float4* sv4 = (const float4*)g_S0;
    const float4* bv4 = (const float4*)b0;
    for (int i = tid; i < 2048; i += 128) {
        int rr = i >> 5, c4 = i & 31;
        int gr = r0 + rr;
        float4 v = make_float4(0.f, 0.f, 0.f, 0.f);
        if (gr < NN) {
            float4 sIn = sv4[gr * 32 + c4];
            float4 bb  = bv4[c4];
            float  am  = AM[gr];
            v.x = fmaxf(fmaf(am, sIn.x, bb.x), 0.f);
            v.y = fmaxf(fmaf(am, sIn.y, bb.y), 0.f);
            v.z = fmaxf(fmaf(am, sIn.z, bb.z), 0.f);
            v.w = fmaxf(fmaf(am, sIn.w, bb.w), 0.f);
        }
        Xs[rr][c4 * 4 + 0] = v.x;
        Xs[rr][c4 * 4 + 1] = v.y;
        Xs[rr][c4 * 4 + 2] = v.z;
        Xs[rr][c4 * 4 + 3] = v.w;
    }
    int tx = tid & 15, ty = tid >> 4;
    float acc[8][4];
    #pragma unroll
    for (int i = 0; i < 8; ++i)
        #pragma unroll
        for (int j = 0; j < 4; ++j) acc[i][j] = 0.f;
    const float4* w4 = (const float4*)W1;
    for (int kc = 0; kc < 128; kc += 32) {
        __syncthreads();
        for (int i = tid; i < 512; i += 128) {
            int rr = i >> 4, c4 = i & 15;
            *(float4*)&Ws[rr][c4 * 4] = w4[(kc + rr) * 16 + c4];
        }
        __syncthreads();
        #pragma unroll 8
        for (int k = 0; k < 32; ++k) {
            float wv[4];
            #pragma unroll
            for (int j = 0; j < 4; ++j) wv[j] = Ws[k][tx + 16 * j];
            #pragma unroll
            for (int i = 0; i < 8; ++i) {
                float xvv = Xs[ty * 8 + i][kc + k];
                #pragma unroll
                for (int j = 0; j < 4; ++j) acc[i][j] += xvv * wv[j];
            }
        }
    }
    #pragma unroll
    for (int i = 0; i < 8; ++i) {
        int gr = r0 + ty * 8 + i;
        if (gr < NN) {
            float m = M[gr];
            #pragma unroll
            for (int j = 0; j < 4; ++j) g_P1[gr * 64 + tx + 16 * j] = m * acc[i][j];
        }
    }
}

// ---------------- spmm width 64 ----------------
__global__ void __launch_bounds__(256) k_spmm64() {
    int w = (blockIdx.x * 256 + threadIdx.x) >> 5;
    int lane = threadIdx.x & 31;
    if (w >= NN) return;
    int s = g_rp[w], e = g_rp[w + 1];
    float ax = 0.f, ay = 0.f;
    const float2* Xv = (const float2*)g_P1;
    int j = s;
    for (; j + 1 < e; j += 2) {
        int c0 = g_colP[j], c1 = g_colP[j + 1];
        float v0 = g_vZ[j], v1 = g_vZ[j + 1];
        float2 a = Xv[c0 * 32 + lane];
        float2 b = Xv[c1 * 32 + lane];
        ax += v0 * a.x + v1 * b.x;
        ay += v0 * a.y + v1 * b.y;
    }
    if (j < e) {
        int c = g_colP[j]; float v = g_vZ[j];
        float2 a = Xv[c * 32 + lane];
        ax += v * a.x; ay += v * a.y;
    }
    float2 o; o.x = ax; o.y = ay;
    ((float2*)g_S1)[w * 32 + lane] = o;
}

// ------- GEMM 2: P2 = relu(AM⊙S1 + b1) @ W2, K=64, NO=40 -------
__global__ void __launch_bounds__(256) k_gemm2(const float* __restrict__ AM,
                                               const float* __restrict__ b1,
                                               const float* __restrict__ W2) {
    __shared__ float Xs[32][68];    // pad 68: 4 rows per warp -> distinct banks
    __shared__ float Ws[64 * 40];
    int r0 = blockIdx.x * 32;
    int tid = threadIdx.x;
    const float4* sv4 = (const float4*)g_S1;
    const float4* bv4 = (const float4*)b1;
    for (int i = tid; i < 512; i += 256) {
        int rr = i >> 4, c4 = i & 15;
        int gr = r0 + rr;
        float4 v = make_float4(0.f, 0.f, 0.f, 0.f);
        if (gr < NN) {
            float4 sIn = sv4[gr * 16 + c4];
            float4 bb  = bv4[c4];
            float  am  = AM[gr];
            v.x = fmaxf(fmaf(am, sIn.x, bb.x), 0.f);
            v.y = fmaxf(fmaf(am, sIn.y, bb.y), 0.f);
            v.z = fmaxf(fmaf(am, sIn.z, bb.z), 0.f);
            v.w = fmaxf(fmaf(am, sIn.w, bb.w), 0.f);
        }
        Xs[rr][c4 * 4 + 0] = v.x;
        Xs[rr][c4 * 4 + 1] = v.y;
        Xs[rr][c4 * 4 + 2] = v.z;
        Xs[rr][c4 * 4 + 3] = v.w;
    }
    for (int i = tid; i < 64 * 40; i += 256) Ws[i] = W2[i];
    __syncthreads();
    int row = tid >> 3, cg = tid & 7;
    float acc[5] = {0.f, 0.f, 0.f, 0.f, 0.f};
    #pragma unroll 4
    for (int k = 0; k < 64; ++k) {
        float xv = Xs[row][k];
        #pragma unroll
        for (int j = 0; j < 5; ++j) acc[j] += xv * Ws[k * 40 + cg * 5 + j];
    }
    int gr = r0 + row;
    if (gr < NN) {
        #pragma unroll
        for (int j = 0; j < 5; ++j) g_P2[gr * 40 + cg * 5 + j] = acc[j];
    }
}

// ------- spmm width 40 on adj + b2 + fused log_softmax -> out -------
__global__ void __launch_bounds__(256) k_spmm40_lsm(const float* __restrict__ b2,
                                                    float* __restrict__ out) {
    int w = (blockIdx.x * 256 + threadIdx.x) >> 5;
    int lane = threadIdx.x & 31;
    if (w >= NN) return;
    int s = g_rp[w], e = g_rp[w + 1];
    bool act = lane < 20;
    float ax = 0.f, ay = 0.f;
    for (int j = s; j < e; ++j) {
        int c = g_colP[j];
        float v = g_vA[j];
        if (act) {
            float2 a = *(const float2*)&g_P2[c * 40 + 2 * lane];
            ax += v * a.x;
            ay += v * a.y;
        }
    }
    if (act) {
        ax += b2[2 * lane];
        ay += b2[2 * lane + 1];
    }
    float m = act ? fmaxf(ax, ay) : -INFINITY;
    for (int off = 16; off; off >>= 1) m = fmaxf(m, __shfl_xor_sync(0xffffffffu, m, off));
    float sum = act ? (expf(ax - m) + expf(ay - m)) : 0.f;
    for (int off = 16; off; off >>= 1) sum += __shfl_xor_sync(0xffffffffu, sum, off);
    float lse = m + logf(sum);
    if (act) {
        float2 o;
        o.x = ax - lse;
        o.y = ay - lse;
        *(float2*)&out[w * 40 + 2 * lane] = o;
    }
}

// ---------------- launch ----------------
extern "C" void kernel_launch(void* const* d_in, const int* in_sizes, int n_in,
                              void* d_out, int out_size) {
    const float* x    = (const float*)d_in[0];
    const float* M    = (const float*)d_in[1];
    const float* AM   = (const float*)d_in[2];
    const float* adjv = (const float*)d_in[3];
    const float* adjZ = (const float*)d_in[4];
    const float* W0   = (const float*)d_in[5];
    const float* b0   = (const float*)d_in[6];
    const float* W1   = (const float*)d_in[7];
    const float* b1   = (const float*)d_in[8];
    const float* W2   = (const float*)d_in[9];
    const float* b2   = (const float*)d_in[10];
    const int*   row  = (const int*)d_in[11];
    const int*   col  = (const int*)d_in[12];
    float* out = (float*)d_out;

    (void)in_sizes; (void)n_in; (void)out_size;

    // CSR build
    k_zero<<<98, 512>>>();
    k_hist<<<(EE + 255) / 256, 256>>>(row);
    k_scan1<<<NCH, 256>>>();
    k_scan2<<<1, 1>>>();
    k_scan3<<<NCH, 1024>>>();
    k_scatter<<<(EE + 255) / 256, 256>>>(row, col, adjZ, adjv);

    // layer 0
    k_gemm0<<<(NN + 31) / 32, 128>>>(x, W0, M);
    k_spmm128<<<(NN + 7) / 8, 256>>>();
    // layer 1
    k_gemm1<<<(NN + 63) / 64, 128>>>(AM, b0, W1, M);
    k_spmm64<<<(NN + 7) / 8, 256>>>();
    // layer 2
    k_gemm2<<<(NN + 31) / 32, 256>>>(AM, b1, W2);
    k_spmm40_lsm<<<(NN + 7) / 8, 256>>>(b2, out);
}

// round 4
// speedup vs baseline: 1.2998x; 1.2998x over previous
#include <cuda_runtime.h>
#include <math.h>

#define NN 50000
#define EE 800000
#define NF0 128
#define NF1 64
#define NF2 40
#define NCH 49   /* ceil(NN/1024) */

// ---------------- scratch (__device__ globals; allocation-free) ----------------
__device__ __align__(256) float g_P0[NN * NF0];   // M ⊙ (x @ W0)
__device__ __align__(256) float g_S0[NN * NF0];   // spmm(adjZ, P0)
__device__ __align__(256) float g_P1[NN * NF1];   // M ⊙ (h0 @ W1)
__device__ __align__(256) float g_S1[NN * NF1];   // spmm(adjZ, P1)
__device__ __align__(256) float g_P2[NN * NF2];   // h1 @ W2
__device__ __align__(256) int   g_rp[NN + 1];
__device__ __align__(256) int   g_deg[NN];
__device__ __align__(256) int   g_cur[NN];
__device__ __align__(256) int   g_colP[EE];
__device__ __align__(256) float g_vZ[EE];
__device__ __align__(256) float g_vA[EE];
__device__ __align__(256) int   g_part[NCH];

// ---------------- helpers ----------------
__device__ __forceinline__ unsigned f2tf(float f) {
    unsigned u;
    asm("cvt.rna.tf32.f32 %0, %1;" : "=r"(u) : "f"(f));
    return u;
}

__device__ __forceinline__ void mma_tf32(float c[4],
                                         const unsigned a[4],
                                         const unsigned b[2]) {
    asm volatile(
        "mma.sync.aligned.m16n8k8.row.col.f32.tf32.tf32.f32 "
        "{%0,%1,%2,%3}, {%4,%5,%6,%7}, {%8,%9}, {%0,%1,%2,%3};"
        : "+f"(c[0]), "+f"(c[1]), "+f"(c[2]), "+f"(c[3])
        : "r"(a[0]), "r"(a[1]), "r"(a[2]), "r"(a[3]), "r"(b[0]), "r"(b[1]));
}

// ---------------- CSR build ----------------
__global__ void k_zero() {
    int i = blockIdx.x * blockDim.x + threadIdx.x;
    int stride = gridDim.x * blockDim.x;
    for (int j = i; j < NN; j += stride) { g_deg[j] = 0; g_cur[j] = 0; }
    if (i == 0) g_rp[NN] = EE;
}

__global__ void k_hist(const int* __restrict__ row) {
    int e = blockIdx.x * blockDim.x + threadIdx.x;
    if (e < EE) atomicAdd(&g_deg[row[e]], 1);
}

__global__ void k_scan1() {   // per-chunk sums (chunk = 1024)
    __shared__ int sred[8];
    int base = blockIdx.x * 1024;
    int local = 0;
    #pragma unroll
    for (int j = 0; j < 4; ++j) {
        int i = base + threadIdx.x + j * 256;
        if (i < NN) local += g_deg[i];
    }
    for (int off = 16; off; off >>= 1) local += __shfl_down_sync(0xffffffffu, local, off);
    if ((threadIdx.x & 31) == 0) sred[threadIdx.x >> 5] = local;
    __syncthreads();
    if (threadIdx.x == 0) {
        int s = 0;
        #pragma unroll
        for (int w = 0; w < 8; ++w) s += sred[w];
        g_part[blockIdx.x] = s;
    }
}

__global__ void k_scan2() {   // parallel exclusive scan of 49 partials
    __shared__ int s[64];
    int t = threadIdx.x;
    int v = (t < NCH) ? g_part[t] : 0;
    s[t] = v;
    __syncthreads();
    for (int off = 1; off < 64; off <<= 1) {
        int u = (t >= off) ? s[t - off] : 0;
        __syncthreads();
        s[t] += u;
        __syncthreads();
    }
    if (t < NCH) g_part[t] = s[t] - v;
}

__global__ void k_scan3() {   // per-chunk exclusive scan + offset
    __shared__ int s[1024];
    int i = blockIdx.x * 1024 + threadIdx.x;
    int v = (i < NN) ? g_deg[i] : 0;
    s[threadIdx.x] = v;
    __syncthreads();
    for (int off = 1; off < 1024; off <<= 1) {
        int t = (threadIdx.x >= (unsigned)off) ? s[threadIdx.x - off] : 0;
        __syncthreads();
        s[threadIdx.x] += t;
        __syncthreads();
    }
    if (i < NN) g_rp[i] = g_part[blockIdx.x] + s[threadIdx.x] - v;
}

__global__ void k_scatter(const int* __restrict__ row, const int* __restrict__ col,
                          const float* __restrict__ vZ, const float* __restrict__ vA) {
    int e = blockIdx.x * blockDim.x + threadIdx.x;
    if (e >= EE) return;
    int r = row[e];
    int pos = g_rp[r] + atomicAdd(&g_cur[r], 1);
    g_colP[pos] = col[e];
    g_vZ[pos]   = vZ[e];
    g_vA[pos]   = vA[e];
}

// ======== GEMM 0 (tf32 tensor core): P0 = M ⊙ (x @ W0), 50000x128x128 ========
// block tile 128x128, 256 threads (8 warps in 2(m) x 4(n)); warp tile 64x32.
__global__ void __launch_bounds__(256) k_gemm0(const float* __restrict__ x,
                                               const float* __restrict__ W0,
                                               const float* __restrict__ M) {
    __shared__ float As[128 * 32];   // [m][k^swz], swz = (m&3)<<3
    __shared__ float Bs[32 * 128];   // [k][n^swz], swz = (k&3)<<3
    int r0 = blockIdx.x * 128;
    int tid = threadIdx.x;
    int lane = tid & 31, wid = tid >> 5;
    int m0w = (wid & 1) * 64;
    int n0w = (wid >> 1) * 32;
    int g = lane >> 2, t = lane & 3;

    float acc[4][4][4];
    #pragma unroll
    for (int i = 0; i < 4; ++i)
        #pragma unroll
        for (int j = 0; j < 4; ++j)
            #pragma unroll
            for (int c = 0; c < 4; ++c) acc[i][j][c] = 0.f;

    const float4* xv = (const float4*)x;
    const float4* wv = (const float4*)W0;

    for (int kc = 0; kc < 128; kc += 32) {
        __syncthreads();
        // stage A (128 rows x 32 k), tf32-rounded, swizzled
        #pragma unroll
        for (int it = 0; it < 4; ++it) {
            int i = tid + it * 256;
            int rr = i >> 3, c4 = i & 7;
            int gr = r0 + rr;
            float4 v = (gr < NN) ? xv[gr * 32 + (kc >> 2) + c4]
                                 : make_float4(0.f, 0.f, 0.f, 0.f);
            float4 o;
            o.x = __uint_as_float(f2tf(v.x));
            o.y = __uint_as_float(f2tf(v.y));
            o.z = __uint_as_float(f2tf(v.z));
            o.w = __uint_as_float(f2tf(v.w));
            *(float4*)&As[rr * 32 + ((c4 * 4) ^ ((rr & 3) << 3))] = o;
        }
        // stage B (32 k x 128 n)
        #pragma unroll
        for (int it = 0; it < 4; ++it) {
            int i = tid + it * 256;
            int kr = i >> 5, c4 = i & 31;
            float4 v = wv[(kc + kr) * 32 + c4];
            float4 o;
            o.x = __uint_as_float(f2tf(v.x));
            o.y = __uint_as_float(f2tf(v.y));
            o.z = __uint_as_float(f2tf(v.z));
            o.w = __uint_as_float(f2tf(v.w));
            *(float4*)&Bs[kr * 128 + ((c4 * 4) ^ ((kr & 3) << 3))] = o;
        }
        __syncthreads();

        #pragma unroll
        for (int k8 = 0; k8 < 32; k8 += 8) {
            unsigned af[4][4], bf[4][2];
            #pragma unroll
            for (int mt = 0; mt < 4; ++mt) {
                int m = m0w + mt * 16 + g;
                int sw = (m & 3) << 3;
                af[mt][0] = __float_as_uint(As[m * 32 + ((k8 + t) ^ sw)]);
                af[mt][1] = __float_as_uint(As[(m + 8) * 32 + ((k8 + t) ^ sw)]);
                af[mt][2] = __float_as_uint(As[m * 32 + ((k8 + t + 4) ^ sw)]);
                af[mt][3] = __float_as_uint(As[(m + 8) * 32 + ((k8 + t + 4) ^ sw)]);
            }
            #pragma unroll
            for (int nt = 0; nt < 4; ++nt) {
                int n = n0w + nt * 8 + g;
                bf[nt][0] = __float_as_uint(Bs[(k8 + t) * 128 + (n ^ (t << 3))]);
                bf[nt][1] = __float_as_uint(Bs[(k8 + t + 4) * 128 + (n ^ (t << 3))]);
            }
            #pragma unroll
            for (int mt = 0; mt < 4; ++mt)
                #pragma unroll
                for (int nt = 0; nt < 4; ++nt)
                    mma_tf32(acc[mt][nt], af[mt], bf[nt]);
        }
    }

    // epilogue: scale by M[row], store fp32
    #pragma unroll
    for (int mt = 0; mt < 4; ++mt) {
        int rlo = r0 + m0w + mt * 16 + g;
        int rhi = rlo + 8;
        float mlo = (rlo < NN) ? M[rlo] : 0.f;
        float mhi = (rhi < NN) ? M[rhi] : 0.f;
        #pragma unroll
        for (int nt = 0; nt < 4; ++nt) {
            int cc = n0w + nt * 8 + 2 * t;
            if (rlo < NN) {
                float2 o; o.x = mlo * acc[mt][nt][0]; o.y = mlo * acc[mt][nt][1];
                *(float2*)&g_P0[rlo * 128 + cc] = o;
            }
            if (rhi < NN) {
                float2 o; o.x = mhi * acc[mt][nt][2]; o.y = mhi * acc[mt][nt][3];
                *(float2*)&g_P1[0]; // no-op guard removed below
                float2 oo; oo.x = mhi * acc[mt][nt][2]; oo.y = mhi * acc[mt][nt][3];
                *(float2*)&g_P0[rhi * 128 + cc] = oo;
            }
        }
    }
}

// ---------------- spmm width 128: S0[r] = sum vZ * P0[col] ----------------
__global__ void __launch_bounds__(256) k_spmm128() {
    int w = (blockIdx.x * 256 + threadIdx.x) >> 5;
    int lane = threadIdx.x & 31;
    if (w >= NN) return;
    int s = g_rp[w], e = g_rp[w + 1];
    float4 acc = make_float4(0.f, 0.f, 0.f, 0.f);
    const float4* Xv = (const float4*)g_P0;
    int j = s;
    for (; j + 1 < e; j += 2) {
        int c0 = g_colP[j], c1 = g_colP[j + 1];
        float v0 = g_vZ[j], v1 = g_vZ[j + 1];
        float4 a = Xv[c0 * 32 + lane];
        float4 b = Xv[c1 * 32 + lane];
        acc.x += v0 * a.x + v1 * b.x;
        acc.y += v0 * a.y + v1 * b.y;
        acc.z += v0 * a.z + v1 * b.z;
        acc.w += v0 * a.w + v1 * b.w;
    }
    if (j < e) {
        int c = g_colP[j]; float v = g_vZ[j];
        float4 a = Xv[c * 32 + lane];
        acc.x += v * a.x; acc.y += v * a.y; acc.z += v * a.z; acc.w += v * a.w;
    }
    ((float4*)g_S0)[w * 32 + lane] = acc;
}

// == GEMM 1 (tf32): P1 = M ⊙ (relu(AM⊙S0 + b0) @ W1), 50000x64x128 ==
// block tile 128x64, 256 threads (8 warps in 4(m) x 2(n)); warp tile 32x32.
__global__ void __launch_bounds__(256) k_gemm1(const float* __restrict__ AM,
                                               const float* __restrict__ b0,
                                               const float* __restrict__ W1,
                                               const float* __restrict__ M) {
    __shared__ float As[128 * 32];   // relu(AM*S0+b0), tf32 bits
    __shared__ float Bs[32 * 64];
    int r0 = blockIdx.x * 128;
    int tid = threadIdx.x;
    int lane = tid & 31, wid = tid >> 5;
    int m0w = (wid & 3) * 32;
    int n0w = (wid >> 2) * 32;
    int g = lane >> 2, t = lane & 3;

    float acc[2][4][4];
    #pragma unroll
    for (int i = 0; i < 2; ++i)
        #pragma unroll
        for (int j = 0; j < 4; ++j)
            #pragma unroll
            for (int c = 0; c < 4; ++c) acc[i][j][c] = 0.f;

    const float4* sv = (const float4*)g_S0;
    const float4* bv = (const float4*)b0;
    const float4* wv = (const float4*)W1;

    for (int kc = 0; kc < 128; kc += 32) {
        __syncthreads();
        // stage A with fused relu(AM*s + b0)
        #pragma unroll
        for (int it = 0; it < 4; ++it) {
            int i = tid + it * 256;
            int rr = i >> 3, c4 = i & 7;
            int gr = r0 + rr;
            float4 o = make_float4(0.f, 0.f, 0.f, 0.f);
            if (gr < NN) {
                float4 s4 = sv[gr * 32 + (kc >> 2) + c4];
                float4 bb = bv[(kc >> 2) + c4];
                float am = AM[gr];
                o.x = fmaxf(fmaf(am, s4.x, bb.x), 0.f);
                o.y = fmaxf(fmaf(am, s4.y, bb.y), 0.f);
                o.z = fmaxf(fmaf(am, s4.z, bb.z), 0.f);
                o.w = fmaxf(fmaf(am, s4.w, bb.w), 0.f);
            }
            o.x = __uint_as_float(f2tf(o.x));
            o.y = __uint_as_float(f2tf(o.y));
            o.z = __uint_as_float(f2tf(o.z));
            o.w = __uint_as_float(f2tf(o.w));
            *(float4*)&As[rr * 32 + ((c4 * 4) ^ ((rr & 3) << 3))] = o;
        }
        // stage B (32 k x 64 n)
        #pragma unroll
        for (int it = 0; it < 2; ++it) {
            int i = tid + it * 256;
            int kr = i >> 4, c4 = i & 15;
            float4 v = wv[(kc + kr) * 16 + c4];
            float4 o;
            o.x = __uint_as_float(f2tf(v.x));
            o.y = __uint_as_float(f2tf(v.y));
            o.z = __uint_as_float(f2tf(v.z));
            o.w = __uint_as_float(f2tf(v.w));
            *(float4*)&Bs[kr * 64 + ((c4 * 4) ^ ((kr & 3) << 3))] = o;
        }
        __syncthreads();

        #pragma unroll
        for (int k8 = 0; k8 < 32; k8 += 8) {
            unsigned af[2][4], bf[4][2];
            #pragma unroll
            for (int mt = 0; mt < 2; ++mt) {
                int m = m0w + mt * 16 + g;
                int sw = (m & 3) << 3;
                af[mt][0] = __float_as_uint(As[m * 32 + ((k8 + t) ^ sw)]);
                af[mt][1] = __float_as_uint(As[(m + 8) * 32 + ((k8 + t) ^ sw)]);
                af[mt][2] = __float_as_uint(As[m * 32 + ((k8 + t + 4) ^ sw)]);
                af[mt][3] = __float_as_uint(As[(m + 8) * 32 + ((k8 + t + 4) ^ sw)]);
            }
            #pragma unroll
            for (int nt = 0; nt < 4; ++nt) {
                int n = n0w + nt * 8 + g;
                bf[nt][0] = __float_as_uint(Bs[(k8 + t) * 64 + (n ^ (t << 3))]);
                bf[nt][1] = __float_as_uint(Bs[(k8 + t + 4) * 64 + (n ^ (t << 3))]);
            }
            #pragma unroll
            for (int mt = 0; mt < 2; ++mt)
                #pragma unroll
                for (int nt = 0; nt < 4; ++nt)
                    mma_tf32(acc[mt][nt], af[mt], bf[nt]);
        }
    }

    #pragma unroll
    for (int mt = 0; mt < 2; ++mt) {
        int rlo = r0 + m0w + mt * 16 + g;
        int rhi = rlo + 8;
        float mlo = (rlo < NN) ? M[rlo] : 0.f;
        float mhi = (rhi < NN) ? M[rhi] : 0.f;
        #pragma unroll
        for (int nt = 0; nt < 4; ++nt) {
            int cc = n0w + nt * 8 + 2 * t;
            if (rlo < NN) {
                float2 o; o.x = mlo * acc[mt][nt][0]; o.y = mlo * acc[mt][nt][1];
                *(float2*)&g_P1[rlo * 64 + cc] = o;
            }
            if (rhi < NN) {
                float2 o; o.x = mhi * acc[mt][nt][2]; o.y = mhi * acc[mt][nt][3];
                *(float2*)&g_P1[rhi * 64 + cc] = o;
            }
        }
    }
}

// ---------------- spmm width 64 ----------------
__global__ void __launch_bounds__(256) k_spmm64() {
    int w = (blockIdx.x * 256 + threadIdx.x) >> 5;
    int lane = threadIdx.x & 31;
    if (w >= NN) return;
    int s = g_rp[w], e = g_rp[w + 1];
    float ax = 0.f, ay = 0.f;
    const float2* Xv = (const float2*)g_P1;
    int j = s;
    for (; j + 1 < e; j += 2) {
        int c0 = g_colP[j], c1 = g_colP[j + 1];
        float v0 = g_vZ[j], v1 = g_vZ[j + 1];
        float2 a = Xv[c0 * 32 + lane];
        float2 b = Xv[c1 * 32 + lane];
        ax += v0 * a.x + v1 * b.x;
        ay += v0 * a.y + v1 * b.y;
    }
    if (j < e) {
        int c = g_colP[j]; float v = g_vZ[j];
        float2 a = Xv[c * 32 + lane];
        ax += v * a.x; ay += v * a.y;
    }
    float2 o; o.x = ax; o.y = ay;
    ((float2*)g_S1)[w * 32 + lane] = o;
}

// ------- GEMM 2: P2 = relu(AM⊙S1 + b1) @ W2, K=64, NO=40 (scalar) -------
__global__ void __launch_bounds__(256) k_gemm2(const float* __restrict__ AM,
                                               const float* __restrict__ b1,
                                               const float* __restrict__ W2) {
    __shared__ float Xs[32][68];
    __shared__ float Ws[64 * 40];
    int r0 = blockIdx.x * 32;
    int tid = threadIdx.x;
    const float4* sv4 = (const float4*)g_S1;
    const float4* bv4 = (const float4*)b1;
    for (int i = tid; i < 512; i += 256) {
        int rr = i >> 4, c4 = i & 15;
        int gr = r0 + rr;
        float4 v = make_float4(0.f, 0.f, 0.f, 0.f);
        if (gr < NN) {
            float4 sIn = sv4[gr * 16 + c4];
            float4 bb  = bv4[c4];
            float  am  = AM[gr];
            v.x = fmaxf(fmaf(am, sIn.x, bb.x), 0.f);
            v.y = fmaxf(fmaf(am, sIn.y, bb.y), 0.f);
            v.z = fmaxf(fmaf(am, sIn.z, bb.z), 0.f);
            v.w = fmaxf(fmaf(am, sIn.w, bb.w), 0.f);
        }
        Xs[rr][c4 * 4 + 0] = v.x;
        Xs[rr][c4 * 4 + 1] = v.y;
        Xs[rr][c4 * 4 + 2] = v.z;
        Xs[rr][c4 * 4 + 3] = v.w;
    }
    for (int i = tid; i < 64 * 40; i += 256) Ws[i] = W2[i];
    __syncthreads();
    int row = tid >> 3, cg = tid & 7;
    float acc[5] = {0.f, 0.f, 0.f, 0.f, 0.f};
    #pragma unroll 4
    for (int k = 0; k < 64; ++k) {
        float xv = Xs[row][k];
        #pragma unroll
        for (int j = 0; j < 5; ++j) acc[j] += xv * Ws[k * 40 + cg * 5 + j];
    }
    int gr = r0 + row;
    if (gr < NN) {
        #pragma unroll
        for (int j = 0; j < 5; ++j) g_P2[gr * 40 + cg * 5 + j] = acc[j];
    }
}

// ------- spmm width 40 on adj + b2 + fused log_softmax -> out -------
__global__ void __launch_bounds__(256) k_spmm40_lsm(const float* __restrict__ b2,
                                                    float* __restrict__ out) {
    int w = (blockIdx.x * 256 + threadIdx.x) >> 5;
    int lane = threadIdx.x & 31;
    if (w >= NN) return;
    int s = g_rp[w], e = g_rp[w + 1];
    bool act = lane < 20;
    float ax = 0.f, ay = 0.f;
    for (int j = s; j < e; ++j) {
        int c = g_colP[j];
        float v = g_vA[j];
        if (act) {
            float2 a = *(const float2*)&g_P2[c * 40 + 2 * lane];
            ax += v * a.x;
            ay += v * a.y;
        }
    }
    if (act) {
        ax += b2[2 * lane];
        ay += b2[2 * lane + 1];
    }
    float m = act ? fmaxf(ax, ay) : -INFINITY;
    for (int off = 16; off; off >>= 1) m = fmaxf(m, __shfl_xor_sync(0xffffffffu, m, off));
    float sum = act ? (expf(ax - m) + expf(ay - m)) : 0.f;
    for (int off = 16; off; off >>= 1) sum += __shfl_xor_sync(0xffffffffu, sum, off);
    float lse = m + logf(sum);
    if (act) {
        float2 o;
        o.x = ax - lse;
        o.y = ay - lse;
        *(float2*)&out[w * 40 + 2 * lane] = o;
    }
}

// ---------------- launch ----------------
extern "C" void kernel_launch(void* const* d_in, const int* in_sizes, int n_in,
                              void* d_out, int out_size) {
    const float* x    = (const float*)d_in[0];
    const float* M    = (const float*)d_in[1];
    const float* AM   = (const float*)d_in[2];
    const float* adjv = (const float*)d_in[3];
    const float* adjZ = (const float*)d_in[4];
    const float* W0   = (const float*)d_in[5];
    const float* b0   = (const float*)d_in[6];
    const float* W1   = (const float*)d_in[7];
    const float* b1   = (const float*)d_in[8];
    const float* W2   = (const float*)d_in[9];
    const float* b2   = (const float*)d_in[10];
    const int*   row  = (const int*)d_in[11];
    const int*   col  = (const int*)d_in[12];
    float* out = (float*)d_out;

    (void)in_sizes; (void)n_in; (void)out_size;

    // CSR build
    k_zero<<<98, 512>>>();
    k_hist<<<(EE + 255) / 256, 256>>>(row);
    k_scan1<<<NCH, 256>>>();
    k_scan2<<<1, 64>>>();
    k_scan3<<<NCH, 1024>>>();
    k_scatter<<<(EE + 255) / 256, 256>>>(row, col, adjZ, adjv);

    // layer 0
    k_gemm0<<<(NN + 127) / 128, 256>>>(x, W0, M);
    k_spmm128<<<(NN + 7) / 8, 256>>>();
    // layer 1
    k_gemm1<<<(NN + 127) / 128, 256>>>(AM, b0, W1, M);
    k_spmm64<<<(NN + 7) / 8, 256>>>();
    // layer 2
    k_gemm2<<<(NN + 31) / 32, 256>>>(AM, b1, W2);
    k_spmm40_lsm<<<(NN + 7) / 8, 256>>>(b2, out);
}